// round 2
// baseline (speedup 1.0000x reference)
#include <cuda_runtime.h>
#include <math.h>

#define NN 100000
#define EE 1600000
#define C  128
#define NB_SCAN 98   // ceil(NN/1024)

// ---------------- scratch (device globals; no allocation allowed) ----------
__device__ int   g_cnt[NN];
__device__ int   g_pref[NN];
__device__ int   g_bsum[NB_SCAN];
__device__ int   g_off[NN];
__device__ int   g_cur[NN];
__device__ int   g_srcid[EE];
__device__ float g_dinv[NN];
__device__ float g_hs[(size_t)NN * C];   // (x@W1) * dinv[src], 51.2 MB
__device__ float g_hs2[NN * 2];          // (relu(...)@W2) * dinv[src]

// ---------------- degree / norm --------------------------------------------
__global__ void k_zero() {
    int i = blockIdx.x * blockDim.x + threadIdx.x;
    if (i < NN) g_cnt[i] = 0;
}

__global__ void k_count(const int* __restrict__ dst) {
    int e = blockIdx.x * blockDim.x + threadIdx.x;
    if (e < EE) atomicAdd(&g_cnt[dst[e]], 1);
}

__global__ void k_dinv() {
    int i = blockIdx.x * blockDim.x + threadIdx.x;
    if (i < NN) g_dinv[i] = rsqrtf((float)(g_cnt[i] + 1));  // +1 self loop
}

// ---------------- CSR build (exclusive scan of counts) ---------------------
__global__ void k_scanA() {
    __shared__ int s[1024];
    int i = blockIdx.x * 1024 + threadIdx.x;
    int v = (i < NN) ? g_cnt[i] : 0;
    s[threadIdx.x] = v;
    __syncthreads();
    for (int off = 1; off < 1024; off <<= 1) {
        int t = (threadIdx.x >= off) ? s[threadIdx.x - off] : 0;
        __syncthreads();
        s[threadIdx.x] += t;
        __syncthreads();
    }
    if (i < NN) g_pref[i] = s[threadIdx.x] - v;      // exclusive within block
    if (threadIdx.x == 1023) g_bsum[blockIdx.x] = s[1023];
}

__global__ void k_scanB() {
    int run = 0;
    for (int i = 0; i < NB_SCAN; i++) { int v = g_bsum[i]; g_bsum[i] = run; run += v; }
}

__global__ void k_scanC() {
    int i = blockIdx.x * blockDim.x + threadIdx.x;
    if (i < NN) {
        int o = g_pref[i] + g_bsum[i >> 10];
        g_off[i] = o;
        g_cur[i] = o;
    }
}

__global__ void k_fill(const int* __restrict__ src, const int* __restrict__ dst) {
    int e = blockIdx.x * blockDim.x + threadIdx.x;
    if (e < EE) {
        int d = dst[e];
        int p = atomicAdd(&g_cur[d], 1);
        g_srcid[p] = src[e];
    }
}

// ---------------- GEMM1: hs = (x @ W1) * dinv[row] -------------------------
// Block: 256 threads, computes 64 rows x 128 cols. W1 (64 KB) served from L1.
__global__ void __launch_bounds__(256) k_gemm1(const float* __restrict__ x,
                                               const float* __restrict__ W1) {
    __shared__ float sx[64 * 128];
    int rbase = blockIdx.x * 64;
    int nrows = NN - rbase; if (nrows > 64) nrows = 64;

    const float4* x4 = reinterpret_cast<const float4*>(x) + (size_t)rbase * 32;
    float4* sx4 = reinterpret_cast<float4*>(sx);
    for (int i = threadIdx.x; i < nrows * 32; i += 256) sx4[i] = x4[i];
    __syncthreads();

    int lane = threadIdx.x & 31;
    int w    = threadIdx.x >> 5;
    int c0   = lane * 4;

    float4 acc[8];
#pragma unroll
    for (int r = 0; r < 8; r++) acc[r] = make_float4(0.f, 0.f, 0.f, 0.f);

    const float* xs = sx + (w * 8) * 128;
#pragma unroll 4
    for (int k = 0; k < 128; k++) {
        float4 wv = __ldg(reinterpret_cast<const float4*>(W1 + k * 128 + c0));
#pragma unroll
        for (int r = 0; r < 8; r++) {
            float xv = xs[r * 128 + k];
            acc[r].x = fmaf(xv, wv.x, acc[r].x);
            acc[r].y = fmaf(xv, wv.y, acc[r].y);
            acc[r].z = fmaf(xv, wv.z, acc[r].z);
            acc[r].w = fmaf(xv, wv.w, acc[r].w);
        }
    }

#pragma unroll
    for (int r = 0; r < 8; r++) {
        int row = rbase + w * 8 + r;
        if (row < NN) {
            float d = g_dinv[row];
            float4 o = make_float4(acc[r].x * d, acc[r].y * d, acc[r].z * d, acc[r].w * d);
            reinterpret_cast<float4*>(g_hs)[(size_t)row * 32 + lane] = o;
        }
    }
}

// ---------------- Layer-1 aggregation + ReLU + GEMM2, warp per node --------
// acc = hs[n] + sum_{nbr} hs[nbr];  a1 = relu(dinv[n]*acc + b1);
// hs2[n] = dinv[n] * (a1 @ W2)
__global__ void __launch_bounds__(256) k_agg1(const float* __restrict__ b1,
                                              const float* __restrict__ W2) {
    int gw = (blockIdx.x * 256 + threadIdx.x) >> 5;
    if (gw >= NN) return;
    int lane = threadIdx.x & 31;

    const float4* hs4 = reinterpret_cast<const float4*>(g_hs);
    float4 acc = hs4[(size_t)gw * 32 + lane];          // self loop
    int start = g_off[gw], len = g_cnt[gw];

    // Software-pipelined neighbor loop: prefetch next srcid while summing.
    if (len > 0) {
        int s_next = __ldg(&g_srcid[start]);
        for (int i = 0; i < len - 1; i++) {
            int s = s_next;
            s_next = __ldg(&g_srcid[start + i + 1]);
            float4 v = hs4[(size_t)s * 32 + lane];
            acc.x += v.x; acc.y += v.y; acc.z += v.z; acc.w += v.w;
        }
        float4 v = hs4[(size_t)s_next * 32 + lane];
        acc.x += v.x; acc.y += v.y; acc.z += v.z; acc.w += v.w;
    }

    float dn = g_dinv[gw];
    float4 bb = __ldg(reinterpret_cast<const float4*>(b1) + lane);
    float a0 = fmaxf(fmaf(dn, acc.x, bb.x), 0.f);
    float a1 = fmaxf(fmaf(dn, acc.y, bb.y), 0.f);
    float a2 = fmaxf(fmaf(dn, acc.z, bb.z), 0.f);
    float a3 = fmaxf(fmaf(dn, acc.w, bb.w), 0.f);

    // W2 row-major [128,2]; lane owns channels c0..c0+3 -> floats [lane*8, lane*8+8)
    float4 wA = __ldg(reinterpret_cast<const float4*>(W2) + lane * 2);
    float4 wB = __ldg(reinterpret_cast<const float4*>(W2) + lane * 2 + 1);
    float p0 = a0 * wA.x + a1 * wA.z + a2 * wB.x + a3 * wB.z;
    float p1 = a0 * wA.y + a1 * wA.w + a2 * wB.y + a3 * wB.w;

#pragma unroll
    for (int o = 16; o; o >>= 1) {
        p0 += __shfl_xor_sync(0xffffffffu, p0, o);
        p1 += __shfl_xor_sync(0xffffffffu, p1, o);
    }
    if (lane == 0) {
        g_hs2[2 * gw]     = p0 * dn;
        g_hs2[2 * gw + 1] = p1 * dn;
    }
}

// ---------------- Layer-2 aggregation + bias + log_softmax, warp per node --
__global__ void __launch_bounds__(256) k_agg2(const float* __restrict__ b2,
                                              float* __restrict__ out) {
    int gw = (blockIdx.x * 256 + threadIdx.x) >> 5;
    if (gw >= NN) return;
    int lane = threadIdx.x & 31;

    int start = g_off[gw], len = g_cnt[gw];
    float s0 = 0.f, s1 = 0.f;
    const float2* h2 = reinterpret_cast<const float2*>(g_hs2);
    for (int i = lane; i < len; i += 32) {
        int s = __ldg(&g_srcid[start + i]);
        float2 v = h2[s];
        s0 += v.x; s1 += v.y;
    }
#pragma unroll
    for (int o = 16; o; o >>= 1) {
        s0 += __shfl_xor_sync(0xffffffffu, s0, o);
        s1 += __shfl_xor_sync(0xffffffffu, s1, o);
    }
    if (lane == 0) {
        float2 self = h2[gw];
        float dn = g_dinv[gw];
        float o0 = fmaf(dn, s0 + self.x, b2[0]);
        float o1 = fmaf(dn, s1 + self.y, b2[1]);
        float m  = fmaxf(o0, o1);
        float lse = m + logf(expf(o0 - m) + expf(o1 - m));
        out[2 * gw]     = o0 - lse;
        out[2 * gw + 1] = o1 - lse;
    }
}

// ---------------- launch ----------------------------------------------------
extern "C" void kernel_launch(void* const* d_in, const int* in_sizes, int n_in,
                              void* d_out, int out_size) {
    (void)in_sizes; (void)n_in; (void)out_size;
    const float* x  = (const float*)d_in[0];
    const int*   ei = (const int*)  d_in[1];
    const float* W1 = (const float*)d_in[2];
    const float* b1 = (const float*)d_in[3];
    const float* W2 = (const float*)d_in[4];
    const float* b2 = (const float*)d_in[5];
    const int* src = ei;
    const int* dst = ei + EE;
    float* out = (float*)d_out;

    k_zero <<<(NN + 255) / 256, 256>>>();
    k_count<<<(EE + 255) / 256, 256>>>(dst);
    k_dinv <<<(NN + 255) / 256, 256>>>();
    k_scanA<<<NB_SCAN, 1024>>>();
    k_scanB<<<1, 1>>>();
    k_scanC<<<(NN + 255) / 256, 256>>>();
    k_fill <<<(EE + 255) / 256, 256>>>(src, dst);
    k_gemm1<<<(NN + 63) / 64, 256>>>(x, W1);
    k_agg1 <<<(NN * 32 + 255) / 256, 256>>>(b1, W2);
    k_agg2 <<<(NN * 32 + 255) / 256, 256>>>(b2, out);
}